// round 3
// baseline (speedup 1.0000x reference)
#include <cuda_runtime.h>

#define NN 100000
#define NE 1600000
#define FIN 256
#define NH 4
#define NC 64

struct __align__(32) SP { float4 a; float4 p; };   // per-node a_src + p
struct __align__(32) DN { float4 den; float4 num; }; // accumulators

// Scratch (static __device__ — no allocations allowed)
__device__ float  d_W[12 * FIN];   // 12 folded weight vectors: [as0..3, ad0..3, p0..3]
__device__ float  d_cb;            // bias . fc_w + fc_b
__device__ SP     d_sp[NN];
__device__ float4 d_ad[NN];
__device__ DN     d_dn[NN];

// ---------------------------------------------------------------------------
// K1: fold lin_w with (att_src, att_dst, fc_w) into 12 x 256 vectors + cb.
// ---------------------------------------------------------------------------
__global__ void k_pre(const float* __restrict__ lin_w,
                      const float* __restrict__ att_src,
                      const float* __restrict__ att_dst,
                      const float* __restrict__ bias,
                      const float* __restrict__ fc_w,
                      const float* __restrict__ fc_b) {
    const int j = blockIdx.x;
    const int k = threadIdx.x;   // 0..255 (feature dim)
    if (j < 12) {
        const int g = j >> 2;    // 0 = att_src, 1 = att_dst, 2 = fc_w
        const int h = j & 3;
        const float* coef = (g == 0) ? att_src + h * NC
                          : (g == 1) ? att_dst + h * NC
                                     : fc_w   + h * NC;
        const float* lw = lin_w + (size_t)h * NC * FIN + k;
        float acc = 0.f;
#pragma unroll 8
        for (int c = 0; c < NC; ++c)
            acc += coef[c] * lw[(size_t)c * FIN];
        d_W[j * FIN + k] = acc;
    } else {
        __shared__ float red[256];
        red[k] = bias[k] * fc_w[k];
        __syncthreads();
        for (int s = 128; s; s >>= 1) {
            if (k < s) red[k] += red[k + s];
            __syncthreads();
        }
        if (k == 0) d_cb = red[0] + fc_b[0];
    }
}

// ---------------------------------------------------------------------------
// K2: per-node projections. 8 lanes per node, 4 nodes per warp.
// Lane owns 32 contiguous features -> weight loads are 4-way warp-broadcast,
// x loads are contiguous float4 runs. 3-level shuffle reduce covers all 4
// nodes simultaneously (xor within aligned 8-lane groups).
// ---------------------------------------------------------------------------
__global__ void __launch_bounds__(256) k_proj(const float* __restrict__ x) {
    const int warp = (blockIdx.x * blockDim.x + threadIdx.x) >> 5;
    const int lane = threadIdx.x & 31;
    const int g    = lane >> 3;        // node-in-warp 0..3
    const int sl   = lane & 7;         // sub-lane 0..7
    const int node = warp * 4 + g;     // 25000 warps cover 100000 exactly
    if (node >= NN) return;

    const float4* xr = (const float4*)(x + (size_t)node * FIN) + sl * 8;
    float4 xv[8];
#pragma unroll
    for (int i = 0; i < 8; ++i) xv[i] = xr[i];

    float acc[12];
#pragma unroll
    for (int j = 0; j < 12; ++j) {
        const float4* wr = (const float4*)(d_W + j * FIN) + sl * 8;
        float s = 0.f;
#pragma unroll
        for (int i = 0; i < 8; ++i) {
            const float4 w = __ldg(wr + i);
            s += xv[i].x * w.x + xv[i].y * w.y + xv[i].z * w.z + xv[i].w * w.w;
        }
        acc[j] = s;
    }
#pragma unroll
    for (int j = 0; j < 12; ++j) {
        acc[j] += __shfl_xor_sync(0xffffffffu, acc[j], 4);
        acc[j] += __shfl_xor_sync(0xffffffffu, acc[j], 2);
        acc[j] += __shfl_xor_sync(0xffffffffu, acc[j], 1);
    }
    if (sl == 0) {
        d_sp[node].a = make_float4(acc[0], acc[1], acc[2],  acc[3]);
        d_ad[node]   = make_float4(acc[4], acc[5], acc[6],  acc[7]);
        d_sp[node].p = make_float4(acc[8], acc[9], acc[10], acc[11]);
        d_dn[node].den = make_float4(0.f, 0.f, 0.f, 0.f);
        d_dn[node].num = make_float4(0.f, 0.f, 0.f, 0.f);
    }
}

// ---------------------------------------------------------------------------
// K3: edge pass. edge_index is int32. Softmax max-subtraction is skipped
// (shift-invariant; |logit| <= ~8 so exp is safe in fp32).
// src-side data packed in one 32B sector; den/num packed in one 32B sector.
// ---------------------------------------------------------------------------
__global__ void __launch_bounds__(256) k_edge(const int* __restrict__ ei) {
    const int e = blockIdx.x * blockDim.x + threadIdx.x;
    if (e >= NE) return;
    const int src = ei[e];
    const int dst = ei[NE + e];

    const float4 a = d_sp[src].a;
    const float4 p = d_sp[src].p;
    const float4 b = d_ad[dst];

    float t;
    float4 ex, np;
    t = a.x + b.x; t = t > 0.f ? t : 0.2f * t; ex.x = __expf(t);
    t = a.y + b.y; t = t > 0.f ? t : 0.2f * t; ex.y = __expf(t);
    t = a.z + b.z; t = t > 0.f ? t : 0.2f * t; ex.z = __expf(t);
    t = a.w + b.w; t = t > 0.f ? t : 0.2f * t; ex.w = __expf(t);
    np.x = ex.x * p.x; np.y = ex.y * p.y; np.z = ex.z * p.z; np.w = ex.w * p.w;

    DN* dn = &d_dn[dst];
    asm volatile("red.global.add.v4.f32 [%0], {%1,%2,%3,%4};"
                 :: "l"(&dn->den), "f"(ex.x), "f"(ex.y), "f"(ex.z), "f"(ex.w)
                 : "memory");
    asm volatile("red.global.add.v4.f32 [%0], {%1,%2,%3,%4};"
                 :: "l"(&dn->num), "f"(np.x), "f"(np.y), "f"(np.z), "f"(np.w)
                 : "memory");
}

// ---------------------------------------------------------------------------
// K4: finalize. out[n] = cb + sum_h num/(den + 1e-16)
// ---------------------------------------------------------------------------
__global__ void __launch_bounds__(256) k_final(float* __restrict__ out) {
    const int n = blockIdx.x * blockDim.x + threadIdx.x;
    if (n >= NN) return;
    const float4 d = d_dn[n].den;
    const float4 u = d_dn[n].num;
    out[n] = d_cb
           + u.x / (d.x + 1e-16f)
           + u.y / (d.y + 1e-16f)
           + u.z / (d.z + 1e-16f)
           + u.w / (d.w + 1e-16f);
}

extern "C" void kernel_launch(void* const* d_in, const int* in_sizes, int n_in,
                              void* d_out, int out_size) {
    const float* x       = (const float*)d_in[0];
    const int*   ei      = (const int*)d_in[1];
    const float* lin_w   = (const float*)d_in[2];
    const float* att_src = (const float*)d_in[3];
    const float* att_dst = (const float*)d_in[4];
    const float* bias    = (const float*)d_in[5];
    const float* fc_w    = (const float*)d_in[6];
    const float* fc_b    = (const float*)d_in[7];
    float* out = (float*)d_out;

    k_pre  <<<13, 256>>>(lin_w, att_src, att_dst, bias, fc_w, fc_b);
    k_proj <<<(NN / 4 + 7) / 8, 256>>>(x);              // 4 nodes/warp, 8 warps/block
    k_edge <<<(NE + 255) / 256, 256>>>(ei);
    k_final<<<(NN + 255) / 256, 256>>>(out);
}

// round 4
// speedup vs baseline: 3.2503x; 3.2503x over previous
#include <cuda_runtime.h>

#define NN 100000
#define NE 1600000
#define FIN 256
#define NH 4
#define NC 64

// Scratch (static __device__ — no allocations allowed)
__device__ float  d_W[12 * FIN];   // 12 folded weight vectors: [as0..3, ad0..3, p0..3]
__device__ float  d_cb;            // bias . fc_w + fc_b
__device__ float4 d_as[NN];        // per-node a_src, 4 heads
__device__ float4 d_ad[NN];        // per-node a_dst, 4 heads
__device__ float4 d_p [NN];        // per-node p = h . fc_w, 4 heads
__device__ float4 d_den[NN];       // softmax denominators per head
__device__ float4 d_num[NN];       // weighted numerators per head

// ---------------------------------------------------------------------------
// K1: fold lin_w with (att_src, att_dst, fc_w) into 12 x 256 vectors + cb.
// ---------------------------------------------------------------------------
__global__ void k_pre(const float* __restrict__ lin_w,
                      const float* __restrict__ att_src,
                      const float* __restrict__ att_dst,
                      const float* __restrict__ bias,
                      const float* __restrict__ fc_w,
                      const float* __restrict__ fc_b) {
    const int j = blockIdx.x;
    const int k = threadIdx.x;   // 0..255 (feature dim)
    if (j < 12) {
        const int g = j >> 2;    // 0 = att_src, 1 = att_dst, 2 = fc_w
        const int h = j & 3;
        const float* coef = (g == 0) ? att_src + h * NC
                          : (g == 1) ? att_dst + h * NC
                                     : fc_w   + h * NC;
        const float* lw = lin_w + (size_t)h * NC * FIN + k;
        float acc = 0.f;
#pragma unroll 8
        for (int c = 0; c < NC; ++c)
            acc += coef[c] * lw[(size_t)c * FIN];
        d_W[j * FIN + k] = acc;
    } else {
        __shared__ float red[256];
        red[k] = bias[k] * fc_w[k];
        __syncthreads();
        for (int s = 128; s; s >>= 1) {
            if (k < s) red[k] += red[k + s];
            __syncthreads();
        }
        if (k == 0) d_cb = red[0] + fc_b[0];
    }
}

// ---------------------------------------------------------------------------
// K2: per-node projections, smem-staged.
// Block = 256 threads handles 32 nodes. x tile + all 12 weight vectors staged
// in smem (coalesced global loads). Each warp computes 4 nodes; lane =
// (g = node-in-warp, s = k mod 8). Bank math:
//   x:  addr%32 = g*8 + s  (row stride 264, 264%32=8)  -> conflict-free
//   w:  8 consecutive addrs broadcast to 4 lanes each  -> conflict-free
// Reduction over s is 3 xor-shuffle levels (stays inside the 8-lane group).
// ---------------------------------------------------------------------------
__global__ void __launch_bounds__(256) k_proj(const float* __restrict__ x) {
    __shared__ float xs[32][264];
    __shared__ float ws[12 * FIN];

    const int tid = threadIdx.x;
    const int nb  = blockIdx.x * 32;

#pragma unroll
    for (int i = 0; i < 12; ++i)
        ws[tid + i * 256] = d_W[tid + i * 256];

#pragma unroll
    for (int i = 0; i < 32; ++i) {
        const int r = (tid >> 8) + i;            // tid>>8 == 0; r = i
        xs[r][tid & 255] = x[(size_t)(nb + r) * FIN + (tid & 255)];
    }
    __syncthreads();

    const int warp = tid >> 5;
    const int lane = tid & 31;
    const int g    = lane >> 3;
    const int s    = lane & 7;
    const int nl   = warp * 4 + g;               // local node 0..31

    float acc[12];
#pragma unroll
    for (int j = 0; j < 12; ++j) acc[j] = 0.f;

    const float* xrow = xs[nl];
#pragma unroll 4
    for (int t = 0; t < 32; ++t) {
        const int k = t * 8 + s;
        const float xv = xrow[k];
#pragma unroll
        for (int j = 0; j < 12; ++j)
            acc[j] += xv * ws[j * 256 + k];
    }
#pragma unroll
    for (int j = 0; j < 12; ++j) {
        acc[j] += __shfl_xor_sync(0xffffffffu, acc[j], 4);
        acc[j] += __shfl_xor_sync(0xffffffffu, acc[j], 2);
        acc[j] += __shfl_xor_sync(0xffffffffu, acc[j], 1);
    }
    if (s == 0) {
        const int node = nb + nl;
        d_as[node] = make_float4(acc[0], acc[1], acc[2],  acc[3]);
        d_ad[node] = make_float4(acc[4], acc[5], acc[6],  acc[7]);
        d_p [node] = make_float4(acc[8], acc[9], acc[10], acc[11]);
        d_den[node] = make_float4(0.f, 0.f, 0.f, 0.f);
        d_num[node] = make_float4(0.f, 0.f, 0.f, 0.f);
    }
}

// ---------------------------------------------------------------------------
// K3: edge pass, 4 edges per thread (int4 index loads, gather MLP=12).
// edge_index is int32. Softmax max-subtraction skipped (shift-invariant,
// |logit| small). Separate den/num arrays -> REDs hash to different L2 slices.
// ---------------------------------------------------------------------------
__device__ __forceinline__ void edge_one(int src, int dst,
                                         const float4 a, const float4 p) {
    const float4 b = d_ad[dst];
    float t;
    float4 ex, np;
    t = a.x + b.x; t = t > 0.f ? t : 0.2f * t; ex.x = __expf(t);
    t = a.y + b.y; t = t > 0.f ? t : 0.2f * t; ex.y = __expf(t);
    t = a.z + b.z; t = t > 0.f ? t : 0.2f * t; ex.z = __expf(t);
    t = a.w + b.w; t = t > 0.f ? t : 0.2f * t; ex.w = __expf(t);
    np.x = ex.x * p.x; np.y = ex.y * p.y; np.z = ex.z * p.z; np.w = ex.w * p.w;

    asm volatile("red.global.add.v4.f32 [%0], {%1,%2,%3,%4};"
                 :: "l"(&d_den[dst]), "f"(ex.x), "f"(ex.y), "f"(ex.z), "f"(ex.w)
                 : "memory");
    asm volatile("red.global.add.v4.f32 [%0], {%1,%2,%3,%4};"
                 :: "l"(&d_num[dst]), "f"(np.x), "f"(np.y), "f"(np.z), "f"(np.w)
                 : "memory");
}

__global__ void __launch_bounds__(256) k_edge(const int* __restrict__ ei) {
    const int base = (blockIdx.x * 256 + threadIdx.x) * 4;
    if (base >= NE) return;                       // NE % 4 == 0 -> all 4 valid

    const int4 s4 = *(const int4*)(ei + base);
    const int4 d4 = *(const int4*)(ei + NE + base);

    // Issue all src-side gathers up front (high MLP).
    const float4 a0 = d_as[s4.x], a1 = d_as[s4.y], a2 = d_as[s4.z], a3 = d_as[s4.w];
    const float4 p0 = d_p [s4.x], p1 = d_p [s4.y], p2 = d_p [s4.z], p3 = d_p [s4.w];

    edge_one(s4.x, d4.x, a0, p0);
    edge_one(s4.y, d4.y, a1, p1);
    edge_one(s4.z, d4.z, a2, p2);
    edge_one(s4.w, d4.w, a3, p3);
}

// ---------------------------------------------------------------------------
// K4: finalize. out[n] = cb + sum_h num/(den + 1e-16)
// ---------------------------------------------------------------------------
__global__ void __launch_bounds__(256) k_final(float* __restrict__ out) {
    const int n = blockIdx.x * blockDim.x + threadIdx.x;
    if (n >= NN) return;
    const float4 d = d_den[n];
    const float4 u = d_num[n];
    out[n] = d_cb
           + u.x / (d.x + 1e-16f)
           + u.y / (d.y + 1e-16f)
           + u.z / (d.z + 1e-16f)
           + u.w / (d.w + 1e-16f);
}

extern "C" void kernel_launch(void* const* d_in, const int* in_sizes, int n_in,
                              void* d_out, int out_size) {
    const float* x       = (const float*)d_in[0];
    const int*   ei      = (const int*)d_in[1];
    const float* lin_w   = (const float*)d_in[2];
    const float* att_src = (const float*)d_in[3];
    const float* att_dst = (const float*)d_in[4];
    const float* bias    = (const float*)d_in[5];
    const float* fc_w    = (const float*)d_in[6];
    const float* fc_b    = (const float*)d_in[7];
    float* out = (float*)d_out;

    k_pre  <<<13, 256>>>(lin_w, att_src, att_dst, bias, fc_w, fc_b);
    k_proj <<<NN / 32, 256>>>(x);                     // 3125 blocks, 32 nodes each
    k_edge <<<(NE / 4 + 255) / 256, 256>>>(ei);       // 4 edges per thread
    k_final<<<(NN + 255) / 256, 256>>>(out);
}